// round 2
// baseline (speedup 1.0000x reference)
#include <cuda_runtime.h>
#include <cuda_bf16.h>
#include <math.h>

#define Bn   8
#define Cc   256
#define C2   512
#define Hh   128
#define Ww   128
#define HW   16384
#define BHW  131072
#define HID  64

// Scratch (device globals: allocation-free rule)
__device__ float g_x[(size_t)C2 * BHW];       // depthwise output, [c2][b*HW + hw]
__device__ float g_off[(size_t)BHW * 4];      // per-pixel (dx_rgb, dy_rgb, dx_tir, dy_tir), pre-scaled
__device__ float g_p1wT[C2 * HID];            // p1 weights transposed [c][h]
__device__ float g_p2eff[HID * 4];            // folded p2 (mean over 4 groups, * 0.1 * 63.5)
__device__ float g_p2beff[4];
__device__ float g_pooled[Bn * C2];
__device__ float g_mod[Bn * Cc];

// ---------------- prep: transpose p1, fold p2 ----------------
__global__ void prep_kernel(const float* __restrict__ p1w,
                            const float* __restrict__ p2w,
                            const float* __restrict__ p2b) {
    int idx = blockIdx.x * 256 + threadIdx.x;
    if (idx < C2 * HID) {
        int h = idx >> 9, c = idx & 511;   // p1w is [64][512] row-major
        g_p1wT[c * HID + h] = p1w[idx];
    }
    if (blockIdx.x == 0) {
        const float SC = 0.1f * 0.5f * 127.0f * 0.25f;
        if (threadIdx.x < HID) {
            int h = threadIdx.x;
            g_p2eff[h*4+0] = SC*(p2w[0*HID+h]+p2w[2*HID+h]+p2w[4*HID+h]+p2w[6*HID+h]);
            g_p2eff[h*4+1] = SC*(p2w[1*HID+h]+p2w[3*HID+h]+p2w[5*HID+h]+p2w[7*HID+h]);
            g_p2eff[h*4+2] = SC*(p2w[8*HID+h]+p2w[10*HID+h]+p2w[12*HID+h]+p2w[14*HID+h]);
            g_p2eff[h*4+3] = SC*(p2w[9*HID+h]+p2w[11*HID+h]+p2w[13*HID+h]+p2w[15*HID+h]);
        } else if (threadIdx.x < HID + 4) {
            int j = threadIdx.x - HID;
            int base = (j >> 1) * 8 + (j & 1);  // 0,1,8,9
            g_p2beff[j] = SC*(p2b[base]+p2b[base+2]+p2b[base+4]+p2b[base+6]);
        }
    }
}

// ---------------- GAP ----------------
__global__ void gap_kernel(const float* __restrict__ rgb, const float* __restrict__ tir) {
    int bc = blockIdx.x;               // 0..4095
    int b = bc >> 9, c2 = bc & 511;
    const float* src = (c2 < Cc) ? rgb + (size_t)(b * Cc + c2) * HW
                                 : tir + (size_t)(b * Cc + c2 - Cc) * HW;
    float s = 0.f;
    for (int i = threadIdx.x; i < HW; i += 256) s += src[i];
    __shared__ float sm[8];
    #pragma unroll
    for (int o = 16; o; o >>= 1) s += __shfl_xor_sync(0xffffffffu, s, o);
    if ((threadIdx.x & 31) == 0) sm[threadIdx.x >> 5] = s;
    __syncthreads();
    if (threadIdx.x < 8) {
        float v = sm[threadIdx.x];
        #pragma unroll
        for (int o = 4; o; o >>= 1) v += __shfl_xor_sync(0xffu, v, o);
        if (threadIdx.x == 0) g_pooled[bc] = v * (1.0f / (float)HW);
    }
}

// ---------------- modulation ----------------
__global__ void mod_kernel(const float* __restrict__ m1w, const float* __restrict__ m1b,
                           const float* __restrict__ m2w, const float* __restrict__ m2b) {
    int b = blockIdx.x;
    __shared__ float hid[HID];
    __shared__ float pl[C2];
    for (int i = threadIdx.x; i < C2; i += 256) pl[i] = g_pooled[b * C2 + i];
    __syncthreads();
    if (threadIdx.x < HID) {
        float s = m1b[threadIdx.x];
        const float* wr = m1w + threadIdx.x * C2;
        for (int c = 0; c < C2; c++) s = fmaf(wr[c], pl[c], s);
        hid[threadIdx.x] = fmaxf(s, 0.f);
    }
    __syncthreads();
    int o = threadIdx.x;
    float s = m2b[o];
    const float* wr = m2w + o * HID;
    #pragma unroll
    for (int h = 0; h < HID; h++) s = fmaf(wr[h], hid[h], s);
    g_mod[b * Cc + o] = 1.f / (1.f + expf(-s));
}

// ---------------- depthwise 3x3 (SAME, zero pad) ----------------
__global__ void dw_kernel(const float* __restrict__ rgb, const float* __restrict__ tir,
                          const float* __restrict__ dww, const float* __restrict__ dwb) {
    int tile = blockIdx.x;                 // 16 tiles of 32x32
    int tx0 = (tile & 3) * 32, ty0 = (tile >> 2) * 32;
    int c2 = blockIdx.y, b = blockIdx.z;
    const float* src = (c2 < Cc) ? rgb + (size_t)(b * Cc + c2) * HW
                                 : tir + (size_t)(b * Cc + c2 - Cc) * HW;
    __shared__ float t[34][36];
    for (int i = threadIdx.y * 32 + threadIdx.x; i < 34 * 34; i += 256) {
        int ly = i / 34, lx = i % 34;
        int gy = ty0 - 1 + ly, gx = tx0 - 1 + lx;
        float v = 0.f;
        if (gy >= 0 && gy < Hh && gx >= 0 && gx < Ww) v = src[gy * Ww + gx];
        t[ly][lx] = v;
    }
    __syncthreads();
    float w[9];
    #pragma unroll
    for (int k = 0; k < 9; k++) w[k] = dww[c2 * 9 + k];
    float bias = dwb[c2];
    int lx = threadIdx.x;
    int lyB = threadIdx.y * 4;
    float r0a = t[lyB][lx],     r0b = t[lyB][lx+1],     r0c = t[lyB][lx+2];
    float r1a = t[lyB+1][lx],   r1b = t[lyB+1][lx+1],   r1c = t[lyB+1][lx+2];
    float* outp = g_x + (size_t)c2 * BHW + (size_t)b * HW + (ty0 + lyB) * Ww + tx0 + lx;
    #pragma unroll
    for (int r = 0; r < 4; r++) {
        float r2a = t[lyB+2+r][lx], r2b = t[lyB+2+r][lx+1], r2c = t[lyB+2+r][lx+2];
        float o = bias;
        o = fmaf(w[0],r0a, fmaf(w[1],r0b, fmaf(w[2],r0c,
            fmaf(w[3],r1a, fmaf(w[4],r1b, fmaf(w[5],r1c,
            fmaf(w[6],r2a, fmaf(w[7],r2b, fmaf(w[8],r2c, o)))))))));
        outp[r * Ww] = o;
        r0a=r1a; r0b=r1b; r0c=r1c; r1a=r2a; r1b=r2b; r1c=r2c;
    }
}

// ---------------- p1 GEMM (+ReLU) + folded p2 -> 4 offsets/pixel ----------------
// block = 256 thr (8 warps); warp handles 8 pixels x 64 hidden; p1wT in smem.
__global__ void p1p2_kernel(const float* __restrict__ p1b) {
    extern __shared__ float sw[];          // [512][64]
    int tid = threadIdx.x;
    for (int i = tid; i < C2 * HID; i += 256) sw[i] = g_p1wT[i];
    __syncthreads();
    int wid = tid >> 5, ln = tid & 31;
    int pbase = blockIdx.x * 64 + wid * 8;
    float acc[16];
    #pragma unroll
    for (int i = 0; i < 16; i++) acc[i] = 0.f;
    int myp = pbase + (ln >> 2);
    int myc = ln & 3;
    const float* xp = g_x + (size_t)myc * BHW + myp;
    for (int c0 = 0; c0 < C2; c0 += 4) {
        float xr = xp[(size_t)c0 * BHW];
        #pragma unroll
        for (int cc = 0; cc < 4; cc++) {
            float2 w2 = ((const float2*)(sw + (c0 + cc) * HID))[ln];
            #pragma unroll
            for (int pi = 0; pi < 8; pi++) {
                float xv = __shfl_sync(0xffffffffu, xr, pi * 4 + cc);
                acc[pi*2]   = fmaf(w2.x, xv, acc[pi*2]);
                acc[pi*2+1] = fmaf(w2.y, xv, acc[pi*2+1]);
            }
        }
    }
    float b0 = p1b[2*ln], b1 = p1b[2*ln+1];
    float w0[4], w1[4];
    #pragma unroll
    for (int j = 0; j < 4; j++) { w0[j] = g_p2eff[(2*ln)*4+j]; w1[j] = g_p2eff[(2*ln+1)*4+j]; }
    float keep[4] = {0.f, 0.f, 0.f, 0.f};
    #pragma unroll
    for (int pi = 0; pi < 8; pi++) {
        float h0 = fmaxf(acc[pi*2]   + b0, 0.f);
        float h1 = fmaxf(acc[pi*2+1] + b1, 0.f);
        #pragma unroll
        for (int j = 0; j < 4; j++) {
            float v = fmaf(w0[j], h0, w1[j] * h1);
            #pragma unroll
            for (int o = 16; o; o >>= 1) v += __shfl_xor_sync(0xffffffffu, v, o);
            if (ln == pi) keep[j] = v + g_p2beff[j];
        }
    }
    if (ln < 8)
        ((float4*)g_off)[pbase + ln] = make_float4(keep[0], keep[1], keep[2], keep[3]);
}

// ---------------- bilinear sample + mod + quality ----------------
__global__ void sample_kernel(const float* __restrict__ rgb, const float* __restrict__ tir,
                              float* __restrict__ out) {
    int x = threadIdx.x;        // 128
    int y = blockIdx.x;         // 128
    int b = blockIdx.y;         // 8
    __shared__ float smod[Cc];
    for (int i = threadIdx.x; i < Cc; i += 128) smod[i] = g_mod[b * Cc + i];
    __syncthreads();
    int hw = y * Ww + x;
    int p = b * HW + hw;
    float4 off = ((const float4*)g_off)[p];

    float ixr = fminf(fmaxf((float)x + off.x, 0.f), 127.f);
    float iyr = fminf(fmaxf((float)y + off.y, 0.f), 127.f);
    float ixt = fminf(fmaxf((float)x + off.z, 0.f), 127.f);
    float iyt = fminf(fmaxf((float)y + off.w, 0.f), 127.f);

    float fx0r = floorf(ixr), fy0r = floorf(iyr);
    int x0r = (int)fx0r, y0r = (int)fy0r;
    int x1r = min(x0r + 1, 127), y1r = min(y0r + 1, 127);
    float wxr = ixr - fx0r, wyr = iyr - fy0r;
    int i00r = y0r*Ww + x0r, i01r = y0r*Ww + x1r, i10r = y1r*Ww + x0r, i11r = y1r*Ww + x1r;

    float fx0t = floorf(ixt), fy0t = floorf(iyt);
    int x0t = (int)fx0t, y0t = (int)fy0t;
    int x1t = min(x0t + 1, 127), y1t = min(y0t + 1, 127);
    float wxt = ixt - fx0t, wyt = iyt - fy0t;
    int i00t = y0t*Ww + x0t, i01t = y0t*Ww + x1t, i10t = y1t*Ww + x0t, i11t = y1t*Ww + x1t;

    const float* rb = rgb + (size_t)b * Cc * HW;
    const float* tb = tir + (size_t)b * Cc * HW;
    float* outR = out + (size_t)b * Cc * HW + hw;
    float* outT = out + (size_t)Bn * Cc * HW + (size_t)b * Cc * HW + hw;

    float qacc = 0.f;
    #pragma unroll 4
    for (int c = 0; c < Cc; c++) {
        size_t co = (size_t)c * HW;
        float v00 = rb[co + i00r], v01 = rb[co + i01r];
        float v10 = rb[co + i10r], v11 = rb[co + i11r];
        float topr = v00 * (1.f - wxr) + v01 * wxr;
        float botr = v10 * (1.f - wxr) + v11 * wxr;
        float rv = (topr * (1.f - wyr) + botr * wyr) * smod[c];

        float u00 = tb[co + i00t], u01 = tb[co + i01t];
        float u10 = tb[co + i10t], u11 = tb[co + i11t];
        float topt = u00 * (1.f - wxt) + u01 * wxt;
        float bott = u10 * (1.f - wxt) + u11 * wxt;
        float tv = (topt * (1.f - wyt) + bott * wyt) * smod[c];

        outR[co] = rv;
        outT[co] = tv;
        qacc += fabsf(rv - tv);
    }
    float q = 1.f - qacc * (1.f / (float)Cc);
    out[(size_t)2 * Bn * Cc * HW + p] = 1.f / (1.f + expf(-q));
}

extern "C" void kernel_launch(void* const* d_in, const int* in_sizes, int n_in,
                              void* d_out, int out_size) {
    const float* rgb  = (const float*)d_in[0];
    const float* tir  = (const float*)d_in[1];
    const float* dw_w = (const float*)d_in[2];
    const float* dw_b = (const float*)d_in[3];
    const float* p1_w = (const float*)d_in[4];
    const float* p1_b = (const float*)d_in[5];
    const float* p2_w = (const float*)d_in[6];
    const float* p2_b = (const float*)d_in[7];
    const float* m1_w = (const float*)d_in[8];
    const float* m1_b = (const float*)d_in[9];
    const float* m2_w = (const float*)d_in[10];
    const float* m2_b = (const float*)d_in[11];
    float* out = (float*)d_out;

    cudaFuncSetAttribute(p1p2_kernel, cudaFuncAttributeMaxDynamicSharedMemorySize, C2 * HID * 4);

    prep_kernel<<<129, 256>>>(p1_w, p2_w, p2_b);
    gap_kernel<<<Bn * C2, 256>>>(rgb, tir);
    mod_kernel<<<Bn, 256>>>(m1_w, m1_b, m2_w, m2_b);
    dw_kernel<<<dim3(16, C2, Bn), dim3(32, 8)>>>(rgb, tir, dw_w, dw_b);
    p1p2_kernel<<<BHW / 64, 256, C2 * HID * 4>>>(p1_b);
    sample_kernel<<<dim3(Hh, Bn), Ww>>>(rgb, tir, out);
}

// round 3
// speedup vs baseline: 1.5852x; 1.5852x over previous
#include <cuda_runtime.h>
#include <cuda_bf16.h>
#include <math.h>

#define Bn   8
#define Cc   256
#define C2   512
#define Hh   128
#define Ww   128
#define HW   16384
#define BHW  131072
#define HID  64

// Scratch (device globals: allocation-free rule)
__device__ float g_off[(size_t)BHW * 4];      // per-pixel (dx_rgb, dy_rgb, dx_tir, dy_tir), pre-scaled
__device__ float g_p1wT[C2 * HID];            // p1 weights transposed [c][h]
__device__ float g_p2eff[HID * 4];            // folded p2 (mean over 4 groups, * 0.1 * 63.5 * 0.25... see prep)
__device__ float g_p2beff[4];
__device__ float g_pooled[Bn * C2];
__device__ float g_mod[Bn * Cc];

// ---- packed fp32x2 helpers (Blackwell FFMA2 pipe, PTX-only) ----
__device__ __forceinline__ void fma2(unsigned long long& d, unsigned long long a, unsigned long long b) {
    asm("fma.rn.f32x2 %0, %1, %2, %0;" : "+l"(d) : "l"(a), "l"(b));
}
__device__ __forceinline__ unsigned long long pk2(float x) {
    unsigned long long r;
    asm("mov.b64 %0, {%1, %1};" : "=l"(r) : "f"(x));
    return r;
}
__device__ __forceinline__ void upk2(float& lo, float& hi, unsigned long long v) {
    asm("mov.b64 {%0, %1}, %2;" : "=f"(lo), "=f"(hi) : "l"(v));
}

// ---------------- prep: transpose p1, fold p2 ----------------
__global__ void prep_kernel(const float* __restrict__ p1w,
                            const float* __restrict__ p2w,
                            const float* __restrict__ p2b) {
    int idx = blockIdx.x * 256 + threadIdx.x;
    if (idx < C2 * HID) {
        int h = idx >> 9, c = idx & 511;   // p1w is [64][512] row-major
        g_p1wT[c * HID + h] = p1w[idx];
    }
    if (blockIdx.x == 0) {
        const float SC = 0.1f * 0.5f * 127.0f * 0.25f;
        if (threadIdx.x < HID) {
            int h = threadIdx.x;
            g_p2eff[h*4+0] = SC*(p2w[0*HID+h]+p2w[2*HID+h]+p2w[4*HID+h]+p2w[6*HID+h]);
            g_p2eff[h*4+1] = SC*(p2w[1*HID+h]+p2w[3*HID+h]+p2w[5*HID+h]+p2w[7*HID+h]);
            g_p2eff[h*4+2] = SC*(p2w[8*HID+h]+p2w[10*HID+h]+p2w[12*HID+h]+p2w[14*HID+h]);
            g_p2eff[h*4+3] = SC*(p2w[9*HID+h]+p2w[11*HID+h]+p2w[13*HID+h]+p2w[15*HID+h]);
        } else if (threadIdx.x < HID + 4) {
            int j = threadIdx.x - HID;
            int base = (j >> 1) * 8 + (j & 1);  // 0,1,8,9
            g_p2beff[j] = SC*(p2b[base]+p2b[base+2]+p2b[base+4]+p2b[base+6]);
        }
    }
}

// ---------------- GAP ----------------
__global__ void gap_kernel(const float* __restrict__ rgb, const float* __restrict__ tir) {
    int bc = blockIdx.x;               // 0..4095
    int b = bc >> 9, c2 = bc & 511;
    const float* src = (c2 < Cc) ? rgb + (size_t)(b * Cc + c2) * HW
                                 : tir + (size_t)(b * Cc + c2 - Cc) * HW;
    float s = 0.f;
    for (int i = threadIdx.x; i < HW; i += 256) s += src[i];
    __shared__ float sm[8];
    #pragma unroll
    for (int o = 16; o; o >>= 1) s += __shfl_xor_sync(0xffffffffu, s, o);
    if ((threadIdx.x & 31) == 0) sm[threadIdx.x >> 5] = s;
    __syncthreads();
    if (threadIdx.x < 8) {
        float v = sm[threadIdx.x];
        #pragma unroll
        for (int o = 4; o; o >>= 1) v += __shfl_xor_sync(0xffu, v, o);
        if (threadIdx.x == 0) g_pooled[bc] = v * (1.0f / (float)HW);
    }
}

// ---------------- modulation ----------------
__global__ void mod_kernel(const float* __restrict__ m1w, const float* __restrict__ m1b,
                           const float* __restrict__ m2w, const float* __restrict__ m2b) {
    int b = blockIdx.x;
    __shared__ float hid[HID];
    __shared__ float pl[C2];
    for (int i = threadIdx.x; i < C2; i += 256) pl[i] = g_pooled[b * C2 + i];
    __syncthreads();
    if (threadIdx.x < HID) {
        float s = m1b[threadIdx.x];
        const float* wr = m1w + threadIdx.x * C2;
        for (int c = 0; c < C2; c++) s = fmaf(wr[c], pl[c], s);
        hid[threadIdx.x] = fmaxf(s, 0.f);
    }
    __syncthreads();
    int o = threadIdx.x;
    float s = m2b[o];
    const float* wr = m2w + o * HID;
    #pragma unroll
    for (int h = 0; h < HID; h++) s = fmaf(wr[h], hid[h], s);
    g_mod[b * Cc + o] = 1.f / (1.f + expf(-s));
}

// ---------------- FUSED: depthwise 3x3 + p1 GEMM(+ReLU) + folded p2 ----------------
// Block = 256 threads, tile = 32x8 pixels. Channels processed in chunks of 8.
// Stage A: load 8 halo tiles (34x10) + weight chunk. Stage B: dw -> xs smem.
// Stage C: register GEMM, thread = 4 px x 16 hid (32 packed f32x2 accumulators).
#define TW 32
#define TH 8
#define HALO 340   // 10*34
#define CHK 8

__global__ __launch_bounds__(256, 2)
void dwgemm_kernel(const float* __restrict__ rgb, const float* __restrict__ tir,
                   const float* __restrict__ dww, const float* __restrict__ dwb,
                   const float* __restrict__ p1b) {
    __shared__ __align__(16) union {
        struct { float tiles[CHK][HALO]; float xs[CHK][TW*TH]; } s;
        float4 red[4][TW*TH];
    } u;
    __shared__ __align__(16) float wch[C2];      // 8 channels x 64 hid (only CHK*HID=512 used)
    __shared__ float wdw[CHK][10];               // 9 taps + bias

    const int tid = threadIdx.x;
    const int tx0 = blockIdx.x * TW;
    const int ty0 = blockIdx.y * TH;
    const int b   = blockIdx.z;
    const int lx = tid & 31, ly = tid >> 5;

    const int hg = tid >> 6;        // hid group 0..3 (16 hid each)
    const int pg = tid & 63;        // pixel group: pixels pg*4..pg*4+3

    unsigned long long acc[32];
    #pragma unroll
    for (int i = 0; i < 32; i++) acc[i] = 0ULL;

    for (int chunk = 0; chunk < C2 / CHK; chunk++) {
        // ---- Stage A: loads ----
        #pragma unroll
        for (int i = tid; i < CHK * HALO; i += 256) {
            int ch = i / HALO;
            int rem = i - ch * HALO;
            int r = rem / 34, col = rem - r * 34;
            int c2 = chunk * CHK + ch;
            int gy = ty0 + r - 1, gx = tx0 + col - 1;
            float v = 0.f;
            if (gy >= 0 && gy < Hh && gx >= 0 && gx < Ww) {
                const float* src = (c2 < Cc) ? rgb + (size_t)(b * Cc + c2) * HW
                                             : tir + (size_t)(b * Cc + c2 - Cc) * HW;
                v = src[gy * Ww + gx];
            }
            u.s.tiles[ch][rem] = v;
        }
        // weight chunk: contiguous 512 floats of g_p1wT
        wch[tid]       = g_p1wT[chunk * (CHK * HID) + tid];
        wch[tid + 256] = g_p1wT[chunk * (CHK * HID) + tid + 256];
        if (tid < CHK * 10) {
            int cc = tid / 10, k = tid - cc * 10;
            wdw[cc][k] = (k < 9) ? dww[(chunk * CHK + cc) * 9 + k] : dwb[chunk * CHK + cc];
        }
        __syncthreads();

        // ---- Stage B: depthwise for my pixel, 8 channels ----
        #pragma unroll
        for (int cc = 0; cc < CHK; cc++) {
            const float* t = &u.s.tiles[cc][ly * 34 + lx];
            float o = wdw[cc][9];
            o = fmaf(wdw[cc][0], t[0],      fmaf(wdw[cc][1], t[1],      fmaf(wdw[cc][2], t[2],
                fmaf(wdw[cc][3], t[34],     fmaf(wdw[cc][4], t[35],     fmaf(wdw[cc][5], t[36],
                fmaf(wdw[cc][6], t[68],     fmaf(wdw[cc][7], t[69],     fmaf(wdw[cc][8], t[70], o)))))))));
            u.s.xs[cc][ly * TW + lx] = o;
        }
        __syncthreads();

        // ---- Stage C: GEMM accumulate ----
        #pragma unroll
        for (int cc = 0; cc < CHK; cc++) {
            float4 x4 = *(const float4*)&u.s.xs[cc][pg * 4];
            const unsigned long long* wp =
                (const unsigned long long*)&wch[cc * HID + hg * 16];
            unsigned long long w2[8];
            #pragma unroll
            for (int k = 0; k < 8; k++) w2[k] = wp[k];
            unsigned long long xx;
            xx = pk2(x4.x);
            #pragma unroll
            for (int k = 0; k < 8; k++) fma2(acc[0*8+k], w2[k], xx);
            xx = pk2(x4.y);
            #pragma unroll
            for (int k = 0; k < 8; k++) fma2(acc[1*8+k], w2[k], xx);
            xx = pk2(x4.z);
            #pragma unroll
            for (int k = 0; k < 8; k++) fma2(acc[2*8+k], w2[k], xx);
            xx = pk2(x4.w);
            #pragma unroll
            for (int k = 0; k < 8; k++) fma2(acc[3*8+k], w2[k], xx);
        }
        __syncthreads();   // wch/xs consumed before next chunk overwrites
    }

    // ---- Epilogue: bias + ReLU + folded p2 -> partial offsets ----
    float bl[16];
    #pragma unroll
    for (int k = 0; k < 16; k++) bl[k] = p1b[hg * 16 + k];

    #pragma unroll
    for (int j = 0; j < 4; j++) {
        float4 o = make_float4(0.f, 0.f, 0.f, 0.f);
        #pragma unroll
        for (int k = 0; k < 8; k++) {
            float h0, h1;
            upk2(h0, h1, acc[j * 8 + k]);
            h0 = fmaxf(h0 + bl[2 * k], 0.f);
            h1 = fmaxf(h1 + bl[2 * k + 1], 0.f);
            const float* p2 = g_p2eff + (hg * 16 + 2 * k) * 4;
            o.x += p2[0] * h0 + p2[4] * h1;
            o.y += p2[1] * h0 + p2[5] * h1;
            o.z += p2[2] * h0 + p2[6] * h1;
            o.w += p2[3] * h0 + p2[7] * h1;
        }
        u.red[hg][pg * 4 + j] = o;
    }
    __syncthreads();

    // final cross-group reduction: thread t -> pixel t
    {
        float4 s0 = u.red[0][tid], s1 = u.red[1][tid], s2 = u.red[2][tid], s3 = u.red[3][tid];
        float4 s;
        s.x = s0.x + s1.x + s2.x + s3.x + g_p2beff[0];
        s.y = s0.y + s1.y + s2.y + s3.y + g_p2beff[1];
        s.z = s0.z + s1.z + s2.z + s3.z + g_p2beff[2];
        s.w = s0.w + s1.w + s2.w + s3.w + g_p2beff[3];
        int py = ty0 + (tid >> 5), px = tx0 + (tid & 31);
        ((float4*)g_off)[b * HW + py * Ww + px] = s;
    }
}

// ---------------- bilinear sample + mod + quality ----------------
__global__ void sample_kernel(const float* __restrict__ rgb, const float* __restrict__ tir,
                              float* __restrict__ out) {
    int x = threadIdx.x;        // 128
    int y = blockIdx.x;         // 128
    int b = blockIdx.y;         // 8
    __shared__ float smod[Cc];
    for (int i = threadIdx.x; i < Cc; i += 128) smod[i] = g_mod[b * Cc + i];
    __syncthreads();
    int hw = y * Ww + x;
    int p = b * HW + hw;
    float4 off = ((const float4*)g_off)[p];

    float ixr = fminf(fmaxf((float)x + off.x, 0.f), 127.f);
    float iyr = fminf(fmaxf((float)y + off.y, 0.f), 127.f);
    float ixt = fminf(fmaxf((float)x + off.z, 0.f), 127.f);
    float iyt = fminf(fmaxf((float)y + off.w, 0.f), 127.f);

    float fx0r = floorf(ixr), fy0r = floorf(iyr);
    int x0r = (int)fx0r, y0r = (int)fy0r;
    int x1r = min(x0r + 1, 127), y1r = min(y0r + 1, 127);
    float wxr = ixr - fx0r, wyr = iyr - fy0r;
    int i00r = y0r*Ww + x0r, i01r = y0r*Ww + x1r, i10r = y1r*Ww + x0r, i11r = y1r*Ww + x1r;

    float fx0t = floorf(ixt), fy0t = floorf(iyt);
    int x0t = (int)fx0t, y0t = (int)fy0t;
    int x1t = min(x0t + 1, 127), y1t = min(y0t + 1, 127);
    float wxt = ixt - fx0t, wyt = iyt - fy0t;
    int i00t = y0t*Ww + x0t, i01t = y0t*Ww + x1t, i10t = y1t*Ww + x0t, i11t = y1t*Ww + x1t;

    const float* rb = rgb + (size_t)b * Cc * HW;
    const float* tb = tir + (size_t)b * Cc * HW;
    float* outR = out + (size_t)b * Cc * HW + hw;
    float* outT = out + (size_t)Bn * Cc * HW + (size_t)b * Cc * HW + hw;

    float qacc = 0.f;
    #pragma unroll 4
    for (int c = 0; c < Cc; c++) {
        size_t co = (size_t)c * HW;
        float v00 = rb[co + i00r], v01 = rb[co + i01r];
        float v10 = rb[co + i10r], v11 = rb[co + i11r];
        float topr = v00 * (1.f - wxr) + v01 * wxr;
        float botr = v10 * (1.f - wxr) + v11 * wxr;
        float rv = (topr * (1.f - wyr) + botr * wyr) * smod[c];

        float u00 = tb[co + i00t], u01 = tb[co + i01t];
        float u10 = tb[co + i10t], u11 = tb[co + i11t];
        float topt = u00 * (1.f - wxt) + u01 * wxt;
        float bott = u10 * (1.f - wxt) + u11 * wxt;
        float tv = (topt * (1.f - wyt) + bott * wyt) * smod[c];

        outR[co] = rv;
        outT[co] = tv;
        qacc += fabsf(rv - tv);
    }
    float q = 1.f - qacc * (1.f / (float)Cc);
    out[(size_t)2 * Bn * Cc * HW + p] = 1.f / (1.f + expf(-q));
}

extern "C" void kernel_launch(void* const* d_in, const int* in_sizes, int n_in,
                              void* d_out, int out_size) {
    const float* rgb  = (const float*)d_in[0];
    const float* tir  = (const float*)d_in[1];
    const float* dw_w = (const float*)d_in[2];
    const float* dw_b = (const float*)d_in[3];
    const float* p1_w = (const float*)d_in[4];
    const float* p1_b = (const float*)d_in[5];
    const float* p2_w = (const float*)d_in[6];
    const float* p2_b = (const float*)d_in[7];
    const float* m1_w = (const float*)d_in[8];
    const float* m1_b = (const float*)d_in[9];
    const float* m2_w = (const float*)d_in[10];
    const float* m2_b = (const float*)d_in[11];
    float* out = (float*)d_out;

    prep_kernel<<<129, 256>>>(p1_w, p2_w, p2_b);
    gap_kernel<<<Bn * C2, 256>>>(rgb, tir);
    mod_kernel<<<Bn, 256>>>(m1_w, m1_b, m2_w, m2_b);
    dwgemm_kernel<<<dim3(Ww / TW, Hh / TH, Bn), 256>>>(rgb, tir, dw_w, dw_b, p1_b);
    sample_kernel<<<dim3(Hh, Bn), Ww>>>(rgb, tir, out);
}

// round 4
// speedup vs baseline: 2.8525x; 1.7994x over previous
#include <cuda_runtime.h>
#include <cuda_bf16.h>
#include <math.h>
#include <stdint.h>

#define Bn   8
#define Cc   256
#define C2   512
#define Hh   128
#define Ww   128
#define HW   16384
#define BHW  131072
#define HID  64

// Scratch (device globals: allocation-free rule)
__device__ float g_off[(size_t)BHW * 4];      // per-pixel (dx_rgb, dy_rgb, dx_tir, dy_tir), pre-scaled
__device__ float g_p1wT[C2 * HID];            // p1 weights transposed [c][h]
__device__ float g_p2eff[HID * 4];            // folded p2
__device__ float g_p2beff[4];
__device__ float g_pooled[Bn * C2];
__device__ float g_mod[Bn * Cc];

// ---- packed fp32x2 helpers ----
__device__ __forceinline__ void fma2(unsigned long long& d, unsigned long long a, unsigned long long b) {
    asm("fma.rn.f32x2 %0, %1, %2, %0;" : "+l"(d) : "l"(a), "l"(b));
}
__device__ __forceinline__ unsigned long long pk2(float x) {
    unsigned long long r;
    asm("mov.b64 %0, {%1, %1};" : "=l"(r) : "f"(x));
    return r;
}
__device__ __forceinline__ void upk2(float& lo, float& hi, unsigned long long v) {
    asm("mov.b64 {%0, %1}, %2;" : "=f"(lo), "=f"(hi) : "l"(v));
}
// ---- cp.async helpers ----
__device__ __forceinline__ uint32_t smem_u32(const void* p) {
    return (uint32_t)__cvta_generic_to_shared(p);
}
__device__ __forceinline__ void cpa4(uint32_t dst, const float* src, int sz) {
    asm volatile("cp.async.ca.shared.global [%0], [%1], 4, %2;" :: "r"(dst), "l"(src), "r"(sz));
}
__device__ __forceinline__ void cpa_commit() { asm volatile("cp.async.commit_group;"); }
__device__ __forceinline__ void cpa_wait1() { asm volatile("cp.async.wait_group 1;"); }

// ---------------- prep: transpose p1, fold p2 ----------------
__global__ void prep_kernel(const float* __restrict__ p1w,
                            const float* __restrict__ p2w,
                            const float* __restrict__ p2b) {
    int idx = blockIdx.x * 256 + threadIdx.x;
    if (idx < C2 * HID) {
        int h = idx >> 9, c = idx & 511;   // p1w is [64][512] row-major
        g_p1wT[c * HID + h] = p1w[idx];
    }
    if (blockIdx.x == 0) {
        const float SC = 0.1f * 0.5f * 127.0f * 0.25f;
        if (threadIdx.x < HID) {
            int h = threadIdx.x;
            g_p2eff[h*4+0] = SC*(p2w[0*HID+h]+p2w[2*HID+h]+p2w[4*HID+h]+p2w[6*HID+h]);
            g_p2eff[h*4+1] = SC*(p2w[1*HID+h]+p2w[3*HID+h]+p2w[5*HID+h]+p2w[7*HID+h]);
            g_p2eff[h*4+2] = SC*(p2w[8*HID+h]+p2w[10*HID+h]+p2w[12*HID+h]+p2w[14*HID+h]);
            g_p2eff[h*4+3] = SC*(p2w[9*HID+h]+p2w[11*HID+h]+p2w[13*HID+h]+p2w[15*HID+h]);
        } else if (threadIdx.x < HID + 4) {
            int j = threadIdx.x - HID;
            int base = (j >> 1) * 8 + (j & 1);  // 0,1,8,9
            g_p2beff[j] = SC*(p2b[base]+p2b[base+2]+p2b[base+4]+p2b[base+6]);
        }
    }
}

// ---------------- GAP ----------------
__global__ void gap_kernel(const float* __restrict__ rgb, const float* __restrict__ tir) {
    int bc = blockIdx.x;               // 0..4095
    int b = bc >> 9, c2 = bc & 511;
    const float* src = (c2 < Cc) ? rgb + (size_t)(b * Cc + c2) * HW
                                 : tir + (size_t)(b * Cc + c2 - Cc) * HW;
    float s = 0.f;
    for (int i = threadIdx.x; i < HW; i += 256) s += src[i];
    __shared__ float sm[8];
    #pragma unroll
    for (int o = 16; o; o >>= 1) s += __shfl_xor_sync(0xffffffffu, s, o);
    if ((threadIdx.x & 31) == 0) sm[threadIdx.x >> 5] = s;
    __syncthreads();
    if (threadIdx.x < 8) {
        float v = sm[threadIdx.x];
        #pragma unroll
        for (int o = 4; o; o >>= 1) v += __shfl_xor_sync(0xffu, v, o);
        if (threadIdx.x == 0) g_pooled[bc] = v * (1.0f / (float)HW);
    }
}

// ---------------- modulation ----------------
__global__ void mod_kernel(const float* __restrict__ m1w, const float* __restrict__ m1b,
                           const float* __restrict__ m2w, const float* __restrict__ m2b) {
    int b = blockIdx.x;
    __shared__ float hid[HID];
    __shared__ float pl[C2];
    for (int i = threadIdx.x; i < C2; i += 256) pl[i] = g_pooled[b * C2 + i];
    __syncthreads();
    if (threadIdx.x < HID) {
        float s = m1b[threadIdx.x];
        const float* wr = m1w + threadIdx.x * C2;
        for (int c = 0; c < C2; c++) s = fmaf(wr[c], pl[c], s);
        hid[threadIdx.x] = fmaxf(s, 0.f);
    }
    __syncthreads();
    int o = threadIdx.x;
    float s = m2b[o];
    const float* wr = m2w + o * HID;
    #pragma unroll
    for (int h = 0; h < HID; h++) s = fmaf(wr[h], hid[h], s);
    g_mod[b * Cc + o] = 1.f / (1.f + expf(-s));
}

// ---------------- FUSED: depthwise 3x3 + p1 GEMM(+ReLU) + folded p2 ----------------
#define TW 32
#define TH 8
#define HALO 340   // 10*34
#define CHK 8
#define NCHUNK (C2 / CHK)

struct __align__(16) SmemT {
    float tiles[2][CHK * HALO];     // double-buffered halo tiles (cp.async dst)
    float xs[CHK][TW * TH];         // dw output (single buffer, barrier-protected)
    float wch[3][CHK * HID];        // triple-buffered p1 weights
    float wdw[3][CHK * 10];         // triple-buffered dw taps+bias
};

__global__ __launch_bounds__(256, 2)
void dwgemm_kernel(const float* __restrict__ rgb, const float* __restrict__ tir,
                   const float* __restrict__ dww, const float* __restrict__ dwb,
                   const float* __restrict__ p1b) {
    __shared__ union {
        SmemT s;
        float4 red[4][TW * TH];
    } u;

    const int tid = threadIdx.x;
    const int tx0 = blockIdx.x * TW;
    const int ty0 = blockIdx.y * TH;
    const int b   = blockIdx.z;
    const int lx = tid & 31, ly = tid >> 5;

    const int hg = tid >> 6;        // hid group 0..3 (16 hid each)
    const int pg = tid & 63;        // pixel group: pixels pg*4..pg*4+3

    const float* rbase = rgb + (size_t)b * Cc * HW;
    const float* tbase = tir + (size_t)b * Cc * HW;

    const uint32_t tiles_a = smem_u32(u.s.tiles);
    const uint32_t wch_a   = smem_u32(u.s.wch);
    const uint32_t wdw_a   = smem_u32(u.s.wdw);

    // ---- async chunk loader ----
    auto load_chunk = [&](int chunk, int bt, int bw) {
        // halo tiles: CHK*HALO = 2720 words
        #pragma unroll
        for (int i0 = 0; i0 < CHK * HALO; i0 += 256) {
            int i = i0 + tid;
            if (i < CHK * HALO) {
                int ch  = i / HALO;
                int rem = i - ch * HALO;
                int r   = rem / 34, col = rem - r * 34;
                int c2  = chunk * CHK + ch;
                int gy = ty0 + r - 1, gx = tx0 + col - 1;
                bool in = ((unsigned)gy < (unsigned)Hh) & ((unsigned)gx < (unsigned)Ww);
                const float* base = (c2 < Cc) ? rbase + (size_t)c2 * HW
                                              : tbase + (size_t)(c2 - Cc) * HW;
                const float* src = base + (in ? (gy * Ww + gx) : 0);
                cpa4(tiles_a + (bt * (CHK * HALO) + i) * 4, src, in ? 4 : 0);
            }
        }
        // p1 weight chunk (contiguous 512 floats)
        cpa4(wch_a + (bw * (CHK * HID) + tid) * 4,       g_p1wT + chunk * (CHK * HID) + tid, 4);
        cpa4(wch_a + (bw * (CHK * HID) + tid + 256) * 4, g_p1wT + chunk * (CHK * HID) + tid + 256, 4);
        // dw taps + bias (80 words)
        if (tid < CHK * 10) {
            int cc = tid / 10, k = tid - cc * 10;
            const float* src = (k < 9) ? dww + (chunk * CHK + cc) * 9 + k
                                       : dwb + chunk * CHK + cc;
            cpa4(wdw_a + (bw * (CHK * 10) + tid) * 4, src, 4);
        }
    };

    unsigned long long acc[32];
    #pragma unroll
    for (int i = 0; i < 32; i++) acc[i] = 0ULL;

    // prologue: chunk 0 into tile buf 0 / weight slot 0
    load_chunk(0, 0, 0);
    cpa_commit();

    int bw_cur = 0, bw_nxt = 1;
    for (int chunk = 0; chunk < NCHUNK; chunk++) {
        int cur = chunk & 1;
        if (chunk + 1 < NCHUNK) load_chunk(chunk + 1, cur ^ 1, bw_nxt);
        cpa_commit();
        cpa_wait1();            // current chunk's data resident
        __syncthreads();

        // ---- Stage B: depthwise for my pixel, CHK channels ----
        const float* tb0 = &u.s.tiles[cur][ly * 34 + lx];
        const float* wd  = &u.s.wdw[bw_cur][0];
        #pragma unroll
        for (int cc = 0; cc < CHK; cc++) {
            const float* t = tb0 + cc * HALO;
            const float* w = wd + cc * 10;
            float o = w[9];
            o = fmaf(w[0], t[0],  fmaf(w[1], t[1],  fmaf(w[2], t[2],
                fmaf(w[3], t[34], fmaf(w[4], t[35], fmaf(w[5], t[36],
                fmaf(w[6], t[68], fmaf(w[7], t[69], fmaf(w[8], t[70], o)))))))));
            u.s.xs[cc][ly * TW + lx] = o;
        }
        __syncthreads();

        // ---- Stage C: GEMM accumulate ----
        const float* wc0 = &u.s.wch[bw_cur][hg * 16];
        #pragma unroll
        for (int cc = 0; cc < CHK; cc++) {
            float4 x4 = *(const float4*)&u.s.xs[cc][pg * 4];
            const ulonglong2* wp = (const ulonglong2*)(wc0 + cc * HID);
            ulonglong2 q0 = wp[0], q1 = wp[1], q2 = wp[2], q3 = wp[3];
            unsigned long long w2[8] = {q0.x, q0.y, q1.x, q1.y, q2.x, q2.y, q3.x, q3.y};
            unsigned long long xx;
            xx = pk2(x4.x);
            #pragma unroll
            for (int k = 0; k < 8; k++) fma2(acc[0*8+k], w2[k], xx);
            xx = pk2(x4.y);
            #pragma unroll
            for (int k = 0; k < 8; k++) fma2(acc[1*8+k], w2[k], xx);
            xx = pk2(x4.z);
            #pragma unroll
            for (int k = 0; k < 8; k++) fma2(acc[2*8+k], w2[k], xx);
            xx = pk2(x4.w);
            #pragma unroll
            for (int k = 0; k < 8; k++) fma2(acc[3*8+k], w2[k], xx);
        }
        // no trailing sync: next iteration's top sync protects xs/tiles/weights
        bw_cur = bw_nxt;
        bw_nxt = (bw_nxt == 2) ? 0 : bw_nxt + 1;
    }

    // ---- Epilogue: bias + ReLU + folded p2 -> partial offsets ----
    float bl[16];
    #pragma unroll
    for (int k = 0; k < 16; k++) bl[k] = p1b[hg * 16 + k];
    float bo[4] = {g_p2beff[0], g_p2beff[1], g_p2beff[2], g_p2beff[3]};
    __syncthreads();   // done reading SmemT; union red reuse

    #pragma unroll
    for (int j = 0; j < 4; j++) {
        float4 o = make_float4(0.f, 0.f, 0.f, 0.f);
        #pragma unroll
        for (int k = 0; k < 8; k++) {
            float h0, h1;
            upk2(h0, h1, acc[j * 8 + k]);
            h0 = fmaxf(h0 + bl[2 * k], 0.f);
            h1 = fmaxf(h1 + bl[2 * k + 1], 0.f);
            const float* p2 = g_p2eff + (hg * 16 + 2 * k) * 4;
            o.x += p2[0] * h0 + p2[4] * h1;
            o.y += p2[1] * h0 + p2[5] * h1;
            o.z += p2[2] * h0 + p2[6] * h1;
            o.w += p2[3] * h0 + p2[7] * h1;
        }
        u.red[hg][pg * 4 + j] = o;
    }
    __syncthreads();

    // final cross-group reduction: thread t -> pixel t
    {
        float4 s0 = u.red[0][tid], s1 = u.red[1][tid], s2 = u.red[2][tid], s3 = u.red[3][tid];
        float4 s;
        s.x = s0.x + s1.x + s2.x + s3.x + bo[0];
        s.y = s0.y + s1.y + s2.y + s3.y + bo[1];
        s.z = s0.z + s1.z + s2.z + s3.z + bo[2];
        s.w = s0.w + s1.w + s2.w + s3.w + bo[3];
        int py = ty0 + (tid >> 5), px = tx0 + (tid & 31);
        ((float4*)g_off)[b * HW + py * Ww + px] = s;
    }
}

// ---------------- bilinear sample + mod + quality ----------------
__global__ void sample_kernel(const float* __restrict__ rgb, const float* __restrict__ tir,
                              float* __restrict__ out) {
    int x = threadIdx.x;        // 128
    int y = blockIdx.x;         // 128
    int b = blockIdx.y;         // 8
    __shared__ float smod[Cc];
    for (int i = threadIdx.x; i < Cc; i += 128) smod[i] = g_mod[b * Cc + i];
    __syncthreads();
    int hw = y * Ww + x;
    int p = b * HW + hw;
    float4 off = ((const float4*)g_off)[p];

    float ixr = fminf(fmaxf((float)x + off.x, 0.f), 127.f);
    float iyr = fminf(fmaxf((float)y + off.y, 0.f), 127.f);
    float ixt = fminf(fmaxf((float)x + off.z, 0.f), 127.f);
    float iyt = fminf(fmaxf((float)y + off.w, 0.f), 127.f);

    float fx0r = floorf(ixr), fy0r = floorf(iyr);
    int x0r = (int)fx0r, y0r = (int)fy0r;
    int x1r = min(x0r + 1, 127), y1r = min(y0r + 1, 127);
    float wxr = ixr - fx0r, wyr = iyr - fy0r;
    int i00r = y0r*Ww + x0r, i01r = y0r*Ww + x1r, i10r = y1r*Ww + x0r, i11r = y1r*Ww + x1r;

    float fx0t = floorf(ixt), fy0t = floorf(iyt);
    int x0t = (int)fx0t, y0t = (int)fy0t;
    int x1t = min(x0t + 1, 127), y1t = min(y0t + 1, 127);
    float wxt = ixt - fx0t, wyt = iyt - fy0t;
    int i00t = y0t*Ww + x0t, i01t = y0t*Ww + x1t, i10t = y1t*Ww + x0t, i11t = y1t*Ww + x1t;

    const float* rb = rgb + (size_t)b * Cc * HW;
    const float* tb = tir + (size_t)b * Cc * HW;
    float* outR = out + (size_t)b * Cc * HW + hw;
    float* outT = out + (size_t)Bn * Cc * HW + (size_t)b * Cc * HW + hw;

    float qacc = 0.f;
    #pragma unroll 4
    for (int c = 0; c < Cc; c++) {
        size_t co = (size_t)c * HW;
        float v00 = rb[co + i00r], v01 = rb[co + i01r];
        float v10 = rb[co + i10r], v11 = rb[co + i11r];
        float topr = v00 * (1.f - wxr) + v01 * wxr;
        float botr = v10 * (1.f - wxr) + v11 * wxr;
        float rv = (topr * (1.f - wyr) + botr * wyr) * smod[c];

        float u00 = tb[co + i00t], u01 = tb[co + i01t];
        float u10 = tb[co + i10t], u11 = tb[co + i11t];
        float topt = u00 * (1.f - wxt) + u01 * wxt;
        float bott = u10 * (1.f - wxt) + u11 * wxt;
        float tv = (topt * (1.f - wyt) + bott * wyt) * smod[c];

        outR[co] = rv;
        outT[co] = tv;
        qacc += fabsf(rv - tv);
    }
    float q = 1.f - qacc * (1.f / (float)Cc);
    out[(size_t)2 * Bn * Cc * HW + p] = 1.f / (1.f + expf(-q));
}

extern "C" void kernel_launch(void* const* d_in, const int* in_sizes, int n_in,
                              void* d_out, int out_size) {
    const float* rgb  = (const float*)d_in[0];
    const float* tir  = (const float*)d_in[1];
    const float* dw_w = (const float*)d_in[2];
    const float* dw_b = (const float*)d_in[3];
    const float* p1_w = (const float*)d_in[4];
    const float* p1_b = (const float*)d_in[5];
    const float* p2_w = (const float*)d_in[6];
    const float* p2_b = (const float*)d_in[7];
    const float* m1_w = (const float*)d_in[8];
    const float* m1_b = (const float*)d_in[9];
    const float* m2_w = (const float*)d_in[10];
    const float* m2_b = (const float*)d_in[11];
    float* out = (float*)d_out;

    prep_kernel<<<129, 256>>>(p1_w, p2_w, p2_b);
    gap_kernel<<<Bn * C2, 256>>>(rgb, tir);
    mod_kernel<<<Bn, 256>>>(m1_w, m1_b, m2_w, m2_b);
    dwgemm_kernel<<<dim3(Ww / TW, Hh / TH, Bn), 256>>>(rgb, tir, dw_w, dw_b, p1_b);
    sample_kernel<<<dim3(Hh, Bn), Ww>>>(rgb, tir, out);
}